// round 12
// baseline (speedup 1.0000x reference)
#include <cuda_runtime.h>
#include <cuda_fp16.h>
#include <cstdint>

// Problem constants
#define B_  32
#define N_  4096
#define E_  8192
#define D_  128
#define ROWS_TOTAL (B_*N_)        // 131072
#define NEDGE (B_*E_)             // 262144
#define NTILES (ROWS_TOTAL/128)   // 1024 tiles of 128 rows
#define GRIDP 152                 // persistent: 1 CTA per SM

// ---------------- device-global scratch ------------------------------------------
__device__ __half g_agg[B_*N_*D_];     // 32MB fp16 aggregation buffer
// repacked fp16 weights (half offsets):
//   [0]      Wx_zr : 256 n x 128 k   (kernel cols 0..255, transposed)
//   [32768]  Wh_zr : 256 n x 128 k   (rker  cols 0..255)
//   [65536]  Wh_h  : 128 n x 128 k   (rker  cols 256..383)
//   [81920]  Wx_h  : 128 n x 128 k   (kernel cols 256..383)
__device__ __half g_wt[2*384*128];

// ---------------- smem layout (bytes), 1 CTA/SM ----------------------------------
// all tiles: 256B rows, XOR swizzle: chunk' = chunk ^ (row&7)   (16B chunks)
#define OFF_BIAS  0                 // 768 floats
#define OFF_AG    4096              // agg  128x256B (32768)
#define OFF_AH    36864             // h    128x256B (32768)
#define OFF_B0    69632             // B buf: Wx_zr / later Wh_h+Wx_h (65536)
#define OFF_B1    135168            // B buf: Wh_zr / later z|r exchange (65536)
#define SMEM_TOTAL 200704

__device__ __forceinline__ uint32_t smem_u32(const void* p) {
    uint32_t a;
    asm("{ .reg .u64 t; cvta.to.shared.u64 t, %1; cvt.u32.u64 %0, t; }" : "=r"(a) : "l"(p));
    return a;
}
__device__ __forceinline__ void ldsm4(uint32_t d[4], uint32_t addr) {
    asm volatile("ldmatrix.sync.aligned.m8n8.x4.shared.b16 {%0,%1,%2,%3}, [%4];"
                 : "=r"(d[0]), "=r"(d[1]), "=r"(d[2]), "=r"(d[3]) : "r"(addr));
}
__device__ __forceinline__ void mma_16816(float c[4], const uint32_t a[4], uint32_t b0, uint32_t b1) {
    asm volatile(
        "mma.sync.aligned.m16n8k16.row.col.f32.f16.f16.f32 "
        "{%0,%1,%2,%3}, {%4,%5,%6,%7}, {%8,%9}, {%0,%1,%2,%3};"
        : "+f"(c[0]), "+f"(c[1]), "+f"(c[2]), "+f"(c[3])
        : "r"(a[0]), "r"(a[1]), "r"(a[2]), "r"(a[3]), "r"(b0), "r"(b1));
}
__device__ __forceinline__ float tanh_ap(float x) {
    float y; asm("tanh.approx.f32 %0, %1;" : "=f"(y) : "f"(x)); return y;
}
__device__ __forceinline__ float sigf(float x) { return fmaf(0.5f, tanh_ap(0.5f * x), 0.5f); }

#define CP_ASYNC16(dst, src) \
    asm volatile("cp.async.cg.shared.global [%0], [%1], 16;" :: "r"(dst), "l"(src) : "memory")
#define CP_COMMIT() asm volatile("cp.async.commit_group;" ::: "memory")
#define CP_WAIT(n)  asm volatile("cp.async.wait_group %0;" :: "n"(n) : "memory")

// exchange tile: [row][col 0..255] halves, 512B rows, chunk' = chunk ^ ((row&7)<<2)
__device__ __forceinline__ uint32_t ex_off(int row, int col) {
    return (uint32_t)(row * 512 + ((((col >> 3) ^ ((row & 7) << 2))) << 4) + (col & 7) * 2);
}
// 256B-row swizzled tile: byte offset of half 'col' in 'row'
__device__ __forceinline__ uint32_t tl_off(int row, int col) {
    return (uint32_t)(row * 256 + ((((col >> 3) ^ (row & 7))) << 4) + (col & 7) * 2);
}

// ================================================================================
// Kernel 1: repack weights into g_wt blocks (transposed, fp16)
// ================================================================================
__global__ void prep_w_kernel(const float* __restrict__ kern, const float* __restrict__ rker) {
    int i = blockIdx.x * blockDim.x + threadIdx.x;
    if (i >= 2 * 384 * 128) return;
    float v;
    if (i < 65536) {                       // Wx_zr | Wh_zr
        int mat = i >> 15, n = (i >> 7) & 255, k = i & 127;
        const float* W = mat ? rker : kern;
        v = W[k * 384 + n];
    } else {                               // Wh_h | Wx_h
        int j = i - 65536;
        int mat = j >> 14, n = (j >> 7) & 127, k = j & 127;
        const float* W = mat ? kern : rker;
        v = W[k * 384 + 256 + n];
    }
    g_wt[i] = __float2half_rn(v);
}

// ================================================================================
// Kernel 2: zero the fp16 aggregation scratch (32MB)
// ================================================================================
__global__ void zero_agg_kernel() {
    const uint4 z = make_uint4(0u, 0u, 0u, 0u);
    int n16 = (B_ * N_ * D_ * 2) / 16;
    for (int i = blockIdx.x * blockDim.x + threadIdx.x; i < n16; i += gridDim.x * blockDim.x)
        reinterpret_cast<uint4*>(g_agg)[i] = z;
}

// ================================================================================
// Kernel 3: scatter-add into fp16 g_agg (2 edges/warp, v4.f16x2 REDG)
// ================================================================================
__global__ void scatter_kernel(const float* __restrict__ msgs, const int* __restrict__ conn) {
    int gwarp = (blockIdx.x * blockDim.x + threadIdx.x) >> 5;
    int lane  = threadIdx.x & 31;
    int edge  = gwarp * 2 + (lane >> 4);
    if (edge >= NEDGE) return;
    int sub = lane & 15;
    int b   = edge >> 13;
    int tgt;
    if (sub == 0) tgt = conn[edge * 2 + 1];
    tgt = __shfl_sync(0xffffffffu, tgt, lane & 16);
    const float4* mp = reinterpret_cast<const float4*>(msgs) + (size_t)edge * 32 + sub * 2;
    float4 m0 = mp[0];
    float4 m1 = mp[1];
    union { __half2 h; uint32_t u; } p0, p1, p2, p3;
    p0.h = __floats2half2_rn(m0.x, m0.y);
    p1.h = __floats2half2_rn(m0.z, m0.w);
    p2.h = __floats2half2_rn(m1.x, m1.y);
    p3.h = __floats2half2_rn(m1.z, m1.w);
    __half* dst = g_agg + ((size_t)((b << 12) + tgt)) * 128 + sub * 8;
    asm volatile("red.global.add.noftz.v4.f16x2 [%0], {%1, %2, %3, %4};"
                 :: "l"(dst), "r"(p0.u), "r"(p1.u), "r"(p2.u), "r"(p3.u) : "memory");
}

// ================================================================================
// Kernel 4: persistent merged-gate GEMM + GRU epilogue.
// 152 CTAs x 512 threads, 128-row tiles, warp grid 4x4.
// ================================================================================

// async copy of an N-row x 256B tile into swizzled smem
__device__ __forceinline__ void cp_tile(uint32_t dst, const __half* src, int nchunks, int tid) {
    const char* s = reinterpret_cast<const char*>(src);
    for (int c = tid; c < nchunks; c += 512) {
        int row = c >> 4, c16 = c & 15;
        CP_ASYNC16(dst + (uint32_t)(row * 256 + ((c16 ^ (row & 7)) << 4)), s + (size_t)c * 16);
    }
}

// h tile: fp32 LDG -> fp16 -> swizzled STS (8B stores)
__device__ __forceinline__ void stage_h(char* smem, const float* __restrict__ atom_state,
                                        int row0, int tid) {
    const float4* hp = reinterpret_cast<const float4*>(atom_state + (size_t)row0 * 128);
    float4 hv[8];
#pragma unroll
    for (int k = 0; k < 8; k++) hv[k] = hp[tid + k * 512];
#pragma unroll
    for (int k = 0; k < 8; k++) {
        int idx = tid + k * 512;
        int row = idx >> 5, f4 = idx & 31;
        union { __half2 h2[2]; uint2 u; } cv;
        cv.h2[0] = __floats2half2_rn(hv[k].x, hv[k].y);
        cv.h2[1] = __floats2half2_rn(hv[k].z, hv[k].w);
        uint32_t off = (uint32_t)(row * 256 + (((f4 >> 1) ^ (row & 7)) << 4) + (f4 & 1) * 8);
        *reinterpret_cast<uint2*>(smem + OFF_AH + off) = cv.u;
    }
}

#define ZERO_ACC(NT) do { _Pragma("unroll") \
    for (int mt = 0; mt < 2; mt++) _Pragma("unroll") \
        for (int nt = 0; nt < NT; nt++) \
            acc[mt][nt][0] = acc[mt][nt][1] = acc[mt][nt][2] = acc[mt][nt][3] = 0.f; } while (0)

// acc += A(32x128) @ B(128 x 8*NT)^T ;  swizzled tiles, per-lane constants cA,r8,bt
#define GEMM(NT, AROW, BROW) do { \
    _Pragma("unroll") \
    for (int kc = 0; kc < 4; kc++) { \
        uint32_t swA0 = (uint32_t)(((4*kc + cA)     ^ r8) << 4); \
        uint32_t swA1 = (uint32_t)(((4*kc + 2 + cA) ^ r8) << 4); \
        uint32_t swB  = (uint32_t)(((4*kc + bt)     ^ r8) << 4); \
        uint32_t A0[2][4], A1[2][4]; \
        _Pragma("unroll") \
        for (int mt = 0; mt < 2; mt++) { \
            ldsm4(A0[mt], (AROW) + mt * 4096 + swA0); \
            ldsm4(A1[mt], (AROW) + mt * 4096 + swA1); \
        } \
        _Pragma("unroll") \
        for (int nt = 0; nt < NT; nt++) { \
            uint32_t Bf[4]; \
            ldsm4(Bf, (BROW) + nt * 2048 + swB); \
            _Pragma("unroll") \
            for (int mt = 0; mt < 2; mt++) { \
                mma_16816(acc[mt][nt], A0[mt], Bf[0], Bf[1]); \
                mma_16816(acc[mt][nt], A1[mt], Bf[2], Bf[3]); \
            } \
        } \
    } } while (0)

__global__ void __launch_bounds__(512, 1)
gru_gemm_kernel(const float* __restrict__ atom_state,
                const float* __restrict__ bias,
                float* __restrict__ out)
{
    extern __shared__ char smem[];
    const uint32_t sb = smem_u32(smem);
    const int tid  = threadIdx.x;
    const int wid  = tid >> 5;
    const int lane = tid & 31;
    const int wr   = wid & 3;          // m group (32 rows each, 128 total)
    const int wc   = wid >> 2;         // n group
    const int g4   = lane >> 2;
    const int tig  = lane & 3;
    const int bt   = lane >> 3;        // B chunk select 0..3
    const int cA   = bt >> 1;          // A chunk select 0..1
    const int r8   = lane & 7;

    float* bias_s = reinterpret_cast<float*>(smem + OFF_BIAS);

    int tile = blockIdx.x;

    // ---- prolog: g1{AG, B0=Wx_zr}, g2{B1=Wh_zr}; bias; h tile ----
    cp_tile(sb + OFF_AG, g_agg + (size_t)tile * 128 * 128, 2048, tid);
    cp_tile(sb + OFF_B0, g_wt, 4096, tid);
    CP_COMMIT();
    cp_tile(sb + OFF_B1, g_wt + 32768, 4096, tid);
    CP_COMMIT();
    for (int i = tid; i < 768; i += 512) bias_s[i] = bias[i];
    stage_h(smem, atom_state, tile * 128, tid);

    // per-lane ldsm row bases
    const int arow = wr * 32 + ((bt & 1) << 3) + r8;
    const uint32_t agRow = sb + OFF_AG + (uint32_t)arow * 256;
    const uint32_t ahRow = sb + OFF_AH + (uint32_t)arow * 256;
    const uint32_t bRowM = (uint32_t)((wc * 64 + r8) * 256);   // merged phases
    const uint32_t bRowS = (uint32_t)((wc * 32 + r8) * 256);   // single-gate phases

    float acc[2][8][4];
    __half2 rpk[2][4][2];

    for (; tile < NTILES; tile += GRIDP) {
        const int row0  = tile * 128;
        const int ntile = tile + GRIDP;
        const bool more = ntile < NTILES;

        // ===== P0: acc(z|r) = agg @ Wx_zr =====
        CP_WAIT(1);                       // g1 done (g2 pending)
        __syncthreads();                  // + AH staged visible
        ZERO_ACC(8);
        GEMM(8, agRow, sb + OFF_B0 + bRowM);
        __syncthreads();                  // B0 reads complete
        cp_tile(sb + OFF_B0, g_wt + 65536, 4096, tid);   // g3: Wh_h | Wx_h
        CP_COMMIT();

        // ===== P1: acc += h @ Wh_zr =====
        CP_WAIT(1);                       // g2 done (g3 pending)
        __syncthreads();
        GEMM(8, ahRow, sb + OFF_B1 + bRowM);
        __syncthreads();                  // B1 reads complete

        // ===== exchange: sigma(z|r) -> fp16 tile in B1 region =====
#pragma unroll
        for (int mt = 0; mt < 2; mt++) {
            const int rowA = wr * 32 + mt * 16 + g4;
#pragma unroll
            for (int nt = 0; nt < 8; nt++) {
                int colb = wc * 64 + nt * 8 + tig * 2;
                float cb0 = bias_s[colb]     + bias_s[384 + colb];
                float cb1 = bias_s[colb + 1] + bias_s[384 + colb + 1];
                __half2 vA = __floats2half2_rn(sigf(acc[mt][nt][0] + cb0), sigf(acc[mt][nt][1] + cb1));
                __half2 vB = __floats2half2_rn(sigf(acc[mt][nt][2] + cb0), sigf(acc[mt][nt][3] + cb1));
                *reinterpret_cast<__half2*>(smem + OFF_B1 + ex_off(rowA,     colb)) = vA;
                *reinterpret_cast<__half2*>(smem + OFF_B1 + ex_off(rowA + 8, colb)) = vB;
            }
        }
        CP_WAIT(0);                       // g3 (Wh_h|Wx_h) landed
        __syncthreads();                  // exchange + g3 visible to all

        // ===== P2: acc = h @ Wh_h ; rpk = r*(acc + bh) =====
        ZERO_ACC(4);
        GEMM(4, ahRow, sb + OFF_B0 + bRowS);
#pragma unroll
        for (int mt = 0; mt < 2; mt++) {
            const int rowA = wr * 32 + mt * 16 + g4;
#pragma unroll
            for (int nt = 0; nt < 4; nt++) {
                int colb = wc * 32 + nt * 8 + tig * 2;
                float b0 = bias_s[384 + 256 + colb];
                float b1 = bias_s[384 + 256 + colb + 1];
                float2 rA = __half22float2(*reinterpret_cast<const __half2*>(
                    smem + OFF_B1 + ex_off(rowA,     128 + colb)));
                float2 rB = __half22float2(*reinterpret_cast<const __half2*>(
                    smem + OFF_B1 + ex_off(rowA + 8, 128 + colb)));
                rpk[mt][nt][0] = __floats2half2_rn(rA.x * (acc[mt][nt][0] + b0), rA.y * (acc[mt][nt][1] + b1));
                rpk[mt][nt][1] = __floats2half2_rn(rB.x * (acc[mt][nt][2] + b0), rB.y * (acc[mt][nt][3] + b1));
            }
        }

        // ===== P3: acc = agg @ Wx_h ; epilogue =====
        ZERO_ACC(4);
        GEMM(4, agRow, sb + OFF_B0 + 32768 + bRowS);

#pragma unroll
        for (int mt = 0; mt < 2; mt++) {
            const int rowA = wr * 32 + mt * 16 + g4;
            const int rowB = rowA + 8;
#pragma unroll
            for (int nt = 0; nt < 4; nt++) {
                int colb = wc * 32 + nt * 8 + tig * 2;
                float b0 = bias_s[256 + colb];
                float b1 = bias_s[256 + colb + 1];
                float2 tA = __half22float2(rpk[mt][nt][0]);
                float2 tB = __half22float2(rpk[mt][nt][1]);
                float2 zA = __half22float2(*reinterpret_cast<const __half2*>(
                    smem + OFF_B1 + ex_off(rowA, colb)));
                float2 zB = __half22float2(*reinterpret_cast<const __half2*>(
                    smem + OFF_B1 + ex_off(rowB, colb)));
                float2 hA = __half22float2(*reinterpret_cast<const __half2*>(
                    smem + OFF_AH + tl_off(rowA, colb)));
                float2 hB = __half22float2(*reinterpret_cast<const __half2*>(
                    smem + OFF_AH + tl_off(rowB, colb)));

                float hh0 = tanh_ap(acc[mt][nt][0] + b0 + tA.x);
                float hh1 = tanh_ap(acc[mt][nt][1] + b1 + tA.y);
                float hh2 = tanh_ap(acc[mt][nt][2] + b0 + tB.x);
                float hh3 = tanh_ap(acc[mt][nt][3] + b1 + tB.y);

                float2 oA = make_float2(zA.x * hA.x + (1.f - zA.x) * hh0,
                                        zA.y * hA.y + (1.f - zA.y) * hh1);
                float2 oB = make_float2(zB.x * hB.x + (1.f - zB.x) * hh2,
                                        zB.y * hB.y + (1.f - zB.y) * hh3);
                *reinterpret_cast<float2*>(out + (size_t)(row0 + rowA) * 128 + colb) = oA;
                *reinterpret_cast<float2*>(out + (size_t)(row0 + rowB) * 128 + colb) = oB;
            }
        }

        __syncthreads();                  // all smem reads of this tile done
        if (more) {                       // next tile: g1'{AG', B0'=Wx_zr}, g2'{B1'=Wh_zr}, AH'
            cp_tile(sb + OFF_AG, g_agg + (size_t)ntile * 128 * 128, 2048, tid);
            cp_tile(sb + OFF_B0, g_wt, 4096, tid);
            CP_COMMIT();
            cp_tile(sb + OFF_B1, g_wt + 32768, 4096, tid);
            CP_COMMIT();
            stage_h(smem, atom_state, ntile * 128, tid);
        }
    }
}

// ================================================================================
// Launch
// ================================================================================
extern "C" void kernel_launch(void* const* d_in, const int* in_sizes, int n_in,
                              void* d_out, int out_size) {
    const float* atom_state = (const float*)d_in[0];
    const float* messages   = (const float*)d_in[1];
    const int*   conn       = (const int*)d_in[2];
    const float* kern       = (const float*)d_in[3];
    const float* rker       = (const float*)d_in[4];
    const float* bias       = (const float*)d_in[5];
    float* out = (float*)d_out;

    cudaFuncSetAttribute(gru_gemm_kernel, cudaFuncAttributeMaxDynamicSharedMemorySize, SMEM_TOTAL);

    prep_w_kernel<<<(2 * 384 * 128 + 255) / 256, 256>>>(kern, rker);
    zero_agg_kernel<<<2048, 256>>>();
    scatter_kernel<<<(NEDGE / 2 * 32) / 256, 256>>>(messages, conn);
    gru_gemm_kernel<<<GRIDP, 512, SMEM_TOTAL>>>(atom_state, bias, out);
}